// round 1
// baseline (speedup 1.0000x reference)
#include <cuda_runtime.h>
#include <cstdint>

#define D_MODEL 1024
#define NHEAD   16
#define BS      8
#define NW      512
#define NV      1024

// ---------------- scratch (allocation-free) ----------------
__device__ float g_tln[BS * NW * D_MODEL];                 // 16 MB
__device__ float g_aln[BS * NV * D_MODEL];                 // 32 MB
__device__ float g_q  [BS * NW * D_MODEL];                 // 16 MB
__device__ float g_k  [BS * NV * D_MODEL];                 // 32 MB
__device__ float g_v  [BS * NV * D_MODEL];                 // 32 MB
__device__ float g_attn[(size_t)BS * NHEAD * NW * NV];     // 256 MB: sigmoid scores

// ---------------- LayerNorm: one block per row of 1024 ----------------
__global__ __launch_bounds__(256) void ln_kernel(const float* __restrict__ x,
                                                 const float* __restrict__ w,
                                                 const float* __restrict__ b,
                                                 int dst)
{
    float* y = dst ? g_aln : g_tln;
    int row = blockIdx.x;
    int t   = threadIdx.x;
    float4 xv = reinterpret_cast<const float4*>(x)[(size_t)row * 256 + t];
    float s  = xv.x + xv.y + xv.z + xv.w;
    float ss = xv.x * xv.x + xv.y * xv.y + xv.z * xv.z + xv.w * xv.w;
#pragma unroll
    for (int o = 16; o > 0; o >>= 1) {
        s  += __shfl_xor_sync(0xffffffffu, s,  o);
        ss += __shfl_xor_sync(0xffffffffu, ss, o);
    }
    __shared__ float rs[8], rss[8];
    if ((t & 31) == 0) { rs[t >> 5] = s; rss[t >> 5] = ss; }
    __syncthreads();
    float tot = 0.f, tot2 = 0.f;
#pragma unroll
    for (int i = 0; i < 8; i++) { tot += rs[i]; tot2 += rss[i]; }
    float mean = tot  * (1.f / 1024.f);
    float var  = tot2 * (1.f / 1024.f) - mean * mean;
    float rstd = rsqrtf(var + 1e-5f);
    float4 wv = reinterpret_cast<const float4*>(w)[t];
    float4 bv = reinterpret_cast<const float4*>(b)[t];
    float4 o;
    o.x = (xv.x - mean) * rstd * wv.x + bv.x;
    o.y = (xv.y - mean) * rstd * wv.y + bv.y;
    o.z = (xv.z - mean) * rstd * wv.z + bv.z;
    o.w = (xv.w - mean) * rstd * wv.w + bv.w;
    reinterpret_cast<float4*>(y)[(size_t)row * 256 + t] = o;
}

// ---------------- C[M,1024] = A[M,1024] @ W[1024,1024]^T + bias ----------------
// 128x128x8 tile, 256 threads, 8x8 per thread (4+4 split), float4 smem.
__global__ __launch_bounds__(256) void gemm_nt_bias(int src,
                                                    const float* __restrict__ W,
                                                    const float* __restrict__ bias,
                                                    int dst)
{
    const float* A = src ? g_aln : g_tln;
    float* C = (dst == 0) ? g_q : (dst == 1) ? g_k : g_v;

    __shared__ __align__(16) float As[8][132];
    __shared__ __align__(16) float Bs[8][132];

    int bm = blockIdx.x * 128, bn = blockIdx.y * 128;
    int t  = threadIdx.x;
    int tx = t & 15, ty = t >> 4;
    int lr = t >> 1, lc = (t & 1) << 2;

    const float* Ap = A + (size_t)(bm + lr) * 1024 + lc;
    const float* Wp = W + (size_t)(bn + lr) * 1024 + lc;

    float acc[8][8];
#pragma unroll
    for (int i = 0; i < 8; i++)
#pragma unroll
        for (int j = 0; j < 8; j++) acc[i][j] = 0.f;

    for (int k0 = 0; k0 < 1024; k0 += 8) {
        float4 a4 = *reinterpret_cast<const float4*>(Ap + k0);
        float4 b4 = *reinterpret_cast<const float4*>(Wp + k0);
        __syncthreads();
        As[lc + 0][lr] = a4.x; As[lc + 1][lr] = a4.y;
        As[lc + 2][lr] = a4.z; As[lc + 3][lr] = a4.w;
        Bs[lc + 0][lr] = b4.x; Bs[lc + 1][lr] = b4.y;
        Bs[lc + 2][lr] = b4.z; Bs[lc + 3][lr] = b4.w;
        __syncthreads();
#pragma unroll
        for (int k = 0; k < 8; k++) {
            float ar[8], br[8];
            *reinterpret_cast<float4*>(ar)     = *reinterpret_cast<const float4*>(&As[k][ty * 4]);
            *reinterpret_cast<float4*>(ar + 4) = *reinterpret_cast<const float4*>(&As[k][64 + ty * 4]);
            *reinterpret_cast<float4*>(br)     = *reinterpret_cast<const float4*>(&Bs[k][tx * 4]);
            *reinterpret_cast<float4*>(br + 4) = *reinterpret_cast<const float4*>(&Bs[k][64 + tx * 4]);
#pragma unroll
            for (int i = 0; i < 8; i++)
#pragma unroll
                for (int j = 0; j < 8; j++)
                    acc[i][j] += ar[i] * br[j];
        }
    }

#pragma unroll
    for (int ih = 0; ih < 2; ih++)
#pragma unroll
        for (int i = 0; i < 4; i++) {
            int row = bm + ih * 64 + ty * 4 + i;
            float* Cp = C + (size_t)row * 1024 + bn;
#pragma unroll
            for (int jh = 0; jh < 2; jh++) {
                int col = jh * 64 + tx * 4;
                float4 o;
                o.x = acc[ih * 4 + i][jh * 4 + 0] + bias[bn + col + 0];
                o.y = acc[ih * 4 + i][jh * 4 + 1] + bias[bn + col + 1];
                o.z = acc[ih * 4 + i][jh * 4 + 2] + bias[bn + col + 2];
                o.w = acc[ih * 4 + i][jh * 4 + 3] + bias[bn + col + 3];
                *reinterpret_cast<float4*>(Cp + col) = o;
            }
        }
}

// ---------------- S = sigmoid(Q Kh^T / 8) per (b,h), 64x64 tiles ----------------
__global__ __launch_bounds__(256) void score_kernel()
{
    int bh = blockIdx.z;           // b*16 + h
    int b  = bh >> 4, h = bh & 15;
    int q0 = blockIdx.y * 64;
    int k0 = blockIdx.x * 64;

    __shared__ __align__(16) float Qs[64][68];   // [d][q]
    __shared__ __align__(16) float Ks[64][68];   // [d][k]

    int t  = threadIdx.x;
    int tx = t & 15, ty = t >> 4;
    int lr = t >> 2;
    int lq = (t & 3) * 4;

    const float* Qg = g_q + (size_t)(b * NW + q0 + lr) * 1024 + h * 64;
    const float* Kg = g_k + (size_t)(b * NV + k0 + lr) * 1024 + h * 64;
#pragma unroll
    for (int c = 0; c < 4; c++) {
        int col = lq + c * 16;
        float4 q4 = *reinterpret_cast<const float4*>(Qg + col);
        float4 k4 = *reinterpret_cast<const float4*>(Kg + col);
        Qs[col + 0][lr] = q4.x; Qs[col + 1][lr] = q4.y;
        Qs[col + 2][lr] = q4.z; Qs[col + 3][lr] = q4.w;
        Ks[col + 0][lr] = k4.x; Ks[col + 1][lr] = k4.y;
        Ks[col + 2][lr] = k4.z; Ks[col + 3][lr] = k4.w;
    }
    __syncthreads();

    float acc[4][4];
#pragma unroll
    for (int i = 0; i < 4; i++)
#pragma unroll
        for (int j = 0; j < 4; j++) acc[i][j] = 0.f;

#pragma unroll
    for (int d = 0; d < 64; d++) {
        float4 qv = *reinterpret_cast<const float4*>(&Qs[d][ty * 4]);
        float4 kv = *reinterpret_cast<const float4*>(&Ks[d][tx * 4]);
        float qa[4] = {qv.x, qv.y, qv.z, qv.w};
        float ka[4] = {kv.x, kv.y, kv.z, kv.w};
#pragma unroll
        for (int i = 0; i < 4; i++)
#pragma unroll
            for (int j = 0; j < 4; j++)
                acc[i][j] += qa[i] * ka[j];
    }

    float* Ap = g_attn + ((size_t)bh * NW + q0 + ty * 4) * 1024 + k0 + tx * 4;
#pragma unroll
    for (int i = 0; i < 4; i++) {
        float4 o;
        o.x = 1.f / (1.f + __expf(-0.125f * acc[i][0]));
        o.y = 1.f / (1.f + __expf(-0.125f * acc[i][1]));
        o.z = 1.f / (1.f + __expf(-0.125f * acc[i][2]));
        o.w = 1.f / (1.f + __expf(-0.125f * acc[i][3]));
        *reinterpret_cast<float4*>(Ap + (size_t)i * 1024) = o;
    }
}

// ---------------- out[b,q,h,:] = S @ Vh, 64q x 64d per block, K=1024 ----------------
__global__ __launch_bounds__(256) void av_kernel(float* __restrict__ out)
{
    int bh = blockIdx.y;
    int b  = bh >> 4, h = bh & 15;
    int q0 = blockIdx.x * 64;

    __shared__ __align__(16) float Ss[16][68];   // [k][q]
    __shared__ __align__(16) float Vs[16][64];   // [k][d]

    int t  = threadIdx.x;
    int tx = t & 15, ty = t >> 4;
    int sr = t >> 2,  sc = (t & 3) * 4;          // S chunk: 64 q x 16 k
    int vr = t >> 4,  vc = (t & 15) * 4;         // V chunk: 16 k x 64 d

    const float* Sg = g_attn + ((size_t)bh * NW + q0) * 1024;
    const float* Vg = g_v + (size_t)(b * NV) * 1024 + h * 64;

    float acc[4][4];
#pragma unroll
    for (int i = 0; i < 4; i++)
#pragma unroll
        for (int j = 0; j < 4; j++) acc[i][j] = 0.f;

    for (int kc = 0; kc < 1024; kc += 16) {
        float4 s4 = *reinterpret_cast<const float4*>(Sg + (size_t)sr * 1024 + kc + sc);
        float4 v4 = *reinterpret_cast<const float4*>(Vg + (size_t)(kc + vr) * 1024 + vc);
        __syncthreads();
        Ss[sc + 0][sr] = s4.x; Ss[sc + 1][sr] = s4.y;
        Ss[sc + 2][sr] = s4.z; Ss[sc + 3][sr] = s4.w;
        *reinterpret_cast<float4*>(&Vs[vr][vc]) = v4;
        __syncthreads();
#pragma unroll
        for (int k = 0; k < 16; k++) {
            float4 sv = *reinterpret_cast<const float4*>(&Ss[k][ty * 4]);
            float4 vv = *reinterpret_cast<const float4*>(&Vs[k][tx * 4]);
            float sa[4] = {sv.x, sv.y, sv.z, sv.w};
            float va[4] = {vv.x, vv.y, vv.z, vv.w};
#pragma unroll
            for (int i = 0; i < 4; i++)
#pragma unroll
                for (int j = 0; j < 4; j++)
                    acc[i][j] += sa[i] * va[j];
        }
    }

    float* Op = out + (size_t)(b * NW + q0 + ty * 4) * 1024 + h * 64 + tx * 4;
#pragma unroll
    for (int i = 0; i < 4; i++) {
        float4 o;
        o.x = acc[i][0]; o.y = acc[i][1]; o.z = acc[i][2]; o.w = acc[i][3];
        *reinterpret_cast<float4*>(Op + (size_t)i * 1024) = o;
    }
}

// ---------------- attn.mean over heads ----------------
__global__ __launch_bounds__(256) void mean_kernel(float* __restrict__ mn)
{
    size_t idx4 = (size_t)blockIdx.x * 256 + threadIdx.x;   // float4 index
    size_t base = idx4 * 4;                                  // element index in (b, q*k)
    size_t b    = base >> 19;                                // 512*1024 per batch
    size_t qk   = base & 524287;
    const float* p = g_attn + b * (size_t)(NHEAD * 524288) + qk;
    float4 s = make_float4(0.f, 0.f, 0.f, 0.f);
#pragma unroll
    for (int h = 0; h < NHEAD; h++) {
        float4 v = *reinterpret_cast<const float4*>(p + (size_t)h * 524288);
        s.x += v.x; s.y += v.y; s.z += v.z; s.w += v.w;
    }
    s.x *= 0.0625f; s.y *= 0.0625f; s.z *= 0.0625f; s.w *= 0.0625f;
    *reinterpret_cast<float4*>(mn + base) = s;
}

// ---------------- launch ----------------
extern "C" void kernel_launch(void* const* d_in, const int* in_sizes, int n_in,
                              void* d_out, int out_size)
{
    (void)in_sizes; (void)n_in; (void)out_size;
    const float* text = (const float*)d_in[0];
    const float* av   = (const float*)d_in[1];
    const float* tn_w = (const float*)d_in[2];
    const float* tn_b = (const float*)d_in[3];
    const float* an_w = (const float*)d_in[4];
    const float* an_b = (const float*)d_in[5];
    const float* Wq   = (const float*)d_in[6];
    const float* bq   = (const float*)d_in[7];
    const float* Wk   = (const float*)d_in[8];
    const float* bk   = (const float*)d_in[9];
    const float* Wv   = (const float*)d_in[10];
    const float* bv   = (const float*)d_in[11];

    float* out   = (float*)d_out;
    float* amean = out + (size_t)BS * NW * D_MODEL;

    ln_kernel<<<BS * NW, 256>>>(text, tn_w, tn_b, 0);
    ln_kernel<<<BS * NV, 256>>>(av, an_w, an_b, 1);

    gemm_nt_bias<<<dim3(BS * NW / 128, 8), 256>>>(0, Wq, bq, 0);
    gemm_nt_bias<<<dim3(BS * NV / 128, 8), 256>>>(1, Wk, bk, 1);
    gemm_nt_bias<<<dim3(BS * NV / 128, 8), 256>>>(1, Wv, bv, 2);

    score_kernel<<<dim3(NV / 64, NW / 64, BS * NHEAD), 256>>>();
    av_kernel<<<dim3(NW / 64, BS * NHEAD), 256>>>(out);
    mean_kernel<<<(BS * NW * NV) / (4 * 256), 256>>>(amean);
}

// round 3
// speedup vs baseline: 1.3963x; 1.3963x over previous
#include <cuda_runtime.h>
#include <cuda_bf16.h>
#include <cstdint>

#define D_MODEL 1024
#define NHEAD   16
#define BS      8
#define NW      512
#define NV      1024

// ---------------- scratch (allocation-free) ----------------
__device__ float g_tln[BS * NW * D_MODEL];                 // 16 MB
__device__ float g_aln[BS * NV * D_MODEL];                 // 32 MB
__device__ float g_q  [BS * NW * D_MODEL];                 // 16 MB
__device__ float g_k  [BS * NV * D_MODEL];                 // 32 MB
__device__ float g_v  [BS * NV * D_MODEL];                 // 32 MB
__device__ float g_attn[(size_t)BS * NHEAD * NW * NV];     // 256 MB: sigmoid scores

// ---------------- helpers ----------------
__device__ __forceinline__ uint32_t smem_to_u32(const void* p) {
    uint32_t a;
    asm("{ .reg .u64 t; cvta.to.shared.u64 t, %1; cvt.u32.u64 %0, t; }" : "=r"(a) : "l"(p));
    return a;
}

__device__ __forceinline__ void split2(float x0, float x1, uint32_t& hi, uint32_t& lo) {
    __nv_bfloat16 h0 = __float2bfloat16(x0), h1 = __float2bfloat16(x1);
    float r0 = x0 - __bfloat162float(h0), r1 = x1 - __bfloat162float(h1);
    __nv_bfloat16 l0 = __float2bfloat16(r0), l1 = __float2bfloat16(r1);
    hi = ((uint32_t)__bfloat16_as_ushort(h1) << 16) | __bfloat16_as_ushort(h0);
    lo = ((uint32_t)__bfloat16_as_ushort(l1) << 16) | __bfloat16_as_ushort(l0);
}

#define LDSM_X4(r0, r1, r2, r3, addr) \
    asm volatile("ldmatrix.sync.aligned.m8n8.x4.shared.b16 {%0,%1,%2,%3}, [%4];" \
        : "=r"(r0), "=r"(r1), "=r"(r2), "=r"(r3) : "r"(addr))
#define LDSM_X4_T(r0, r1, r2, r3, addr) \
    asm volatile("ldmatrix.sync.aligned.m8n8.x4.trans.shared.b16 {%0,%1,%2,%3}, [%4];" \
        : "=r"(r0), "=r"(r1), "=r"(r2), "=r"(r3) : "r"(addr))

__device__ __forceinline__ void mma16816(float* c, const uint32_t* a, const uint32_t* b) {
    asm volatile(
        "mma.sync.aligned.m16n8k16.row.col.f32.bf16.bf16.f32 "
        "{%0,%1,%2,%3}, {%4,%5,%6,%7}, {%8,%9}, {%0,%1,%2,%3};"
        : "+f"(c[0]), "+f"(c[1]), "+f"(c[2]), "+f"(c[3])
        : "r"(a[0]), "r"(a[1]), "r"(a[2]), "r"(a[3]), "r"(b[0]), "r"(b[1]));
}

// smem layout per buffer (bytes):
//  A_hi: [128 rows][24 bf16] stride 48B  -> 6144
//  A_lo: +6144
//  B_hi: [16 k rows][136 bf16] stride 272B -> 4352, at +12288
//  B_lo: +16640
#define OFF_AH 0
#define OFF_AL 6144
#define OFF_BH 12288
#define OFF_BL 16640
#define BUF_SZ 20992

// ---------------- tensor-core projection GEMM (mma.sync bf16x3) ----------------
// C[M,1024] = A[M,1024] @ W[1024,1024]^T + bias
__global__ __launch_bounds__(256, 1) void gemm_tc(int src,
                                                  const float* __restrict__ W,
                                                  const float* __restrict__ bias,
                                                  int dst)
{
    __shared__ __align__(16) uint8_t sm[2][BUF_SZ];
    const float* A = src ? g_aln : g_tln;
    float* C = (dst == 0) ? g_q : (dst == 1) ? g_k : g_v;

    int t = threadIdx.x, lane = t & 31, warp = t >> 5;
    int wm = warp >> 2, wn = warp & 3;            // warp grid 2 x 4
    int bm = blockIdx.x * 128, bn = blockIdx.y * 128;

    // staging indices: two float4 per thread for A, two for W
    int r0 = t >> 2,        c40 = t & 3;          // ids 0..255
    int r1 = (t + 256) >> 2, c41 = t & 3;         // ids 256..511 (r1 = r0+64)
    const float4* Ag0 = reinterpret_cast<const float4*>(A + (size_t)(bm + r0) * 1024 + c40 * 4);
    const float4* Ag1 = reinterpret_cast<const float4*>(A + (size_t)(bm + r1) * 1024 + c41 * 4);
    const float4* Wg0 = reinterpret_cast<const float4*>(W + (size_t)(bn + r0) * 1024 + c40 * 4);
    const float4* Wg1 = reinterpret_cast<const float4*>(W + (size_t)(bn + r1) * 1024 + c41 * 4);

    uint32_t smb = smem_to_u32(sm);

    // ldmatrix lane offsets
    uint32_t a_off = (uint32_t)((lane & 15) * 48 + (lane >> 4) * 16);          // within A plane
    uint32_t b_off = (uint32_t)((((lane >> 3) & 1) * 8 + (lane & 7)) * 272 +
                                (lane >> 4) * 16);                              // within B plane

    float acc[4][4][4];
#pragma unroll
    for (int i = 0; i < 4; i++)
#pragma unroll
        for (int j = 0; j < 4; j++)
#pragma unroll
            for (int e = 0; e < 4; e++) acc[i][j][e] = 0.f;

    // ---- staging helper lambdas ----
    auto stage = [&](int buf, float4 va0, float4 va1, float4 vw0, float4 vw1) {
        uint8_t* p = sm[buf];
        uint32_t h0, l0, h1, l1;
        // A row r0
        split2(va0.x, va0.y, h0, l0); split2(va0.z, va0.w, h1, l1);
        *reinterpret_cast<uint2*>(p + OFF_AH + r0 * 48 + c40 * 8) = make_uint2(h0, h1);
        *reinterpret_cast<uint2*>(p + OFF_AL + r0 * 48 + c40 * 8) = make_uint2(l0, l1);
        // A row r1
        split2(va1.x, va1.y, h0, l0); split2(va1.z, va1.w, h1, l1);
        *reinterpret_cast<uint2*>(p + OFF_AH + r1 * 48 + c41 * 8) = make_uint2(h0, h1);
        *reinterpret_cast<uint2*>(p + OFF_AL + r1 * 48 + c41 * 8) = make_uint2(l0, l1);
        // W transposed into [k][n]
        float wv0[4] = {vw0.x, vw0.y, vw0.z, vw0.w};
        float wv1[4] = {vw1.x, vw1.y, vw1.z, vw1.w};
#pragma unroll
        for (int j = 0; j < 4; j++) {
            int k0 = c40 * 4 + j;
            __nv_bfloat16 h = __float2bfloat16(wv0[j]);
            __nv_bfloat16 l = __float2bfloat16(wv0[j] - __bfloat162float(h));
            *reinterpret_cast<__nv_bfloat16*>(p + OFF_BH + k0 * 272 + r0 * 2) = h;
            *reinterpret_cast<__nv_bfloat16*>(p + OFF_BL + k0 * 272 + r0 * 2) = l;
            int k1 = c41 * 4 + j;
            h = __float2bfloat16(wv1[j]);
            l = __float2bfloat16(wv1[j] - __bfloat162float(h));
            *reinterpret_cast<__nv_bfloat16*>(p + OFF_BH + k1 * 272 + r1 * 2) = h;
            *reinterpret_cast<__nv_bfloat16*>(p + OFF_BL + k1 * 272 + r1 * 2) = l;
        }
    };

    // prologue: stage chunk 0
    {
        float4 va0 = Ag0[0], va1 = Ag1[0], vw0 = Wg0[0], vw1 = Wg1[0];
        stage(0, va0, va1, vw0, vw1);
    }
    __syncthreads();

    for (int ch = 0; ch < 64; ch++) {
        int cur = ch & 1;
        float4 va0, va1, vw0, vw1;
        if (ch < 63) {
            va0 = Ag0[(ch + 1) * 4]; va1 = Ag1[(ch + 1) * 4];
            vw0 = Wg0[(ch + 1) * 4]; vw1 = Wg1[(ch + 1) * 4];
        }

        uint32_t base = smb + (uint32_t)(cur * BUF_SZ);

        // load fragments
        uint32_t ah[4][4], al[4][4], bh[4][2], bl[4][2];
#pragma unroll
        for (int mt = 0; mt < 4; mt++) {
            uint32_t ra = base + OFF_AH + (uint32_t)((wm * 64 + mt * 16) * 48) + a_off;
            LDSM_X4(ah[mt][0], ah[mt][1], ah[mt][2], ah[mt][3], ra);
            uint32_t rl = base + OFF_AL + (uint32_t)((wm * 64 + mt * 16) * 48) + a_off;
            LDSM_X4(al[mt][0], al[mt][1], al[mt][2], al[mt][3], rl);
        }
#pragma unroll
        for (int pp = 0; pp < 2; pp++) {
            uint32_t rb = base + OFF_BH + (uint32_t)((wn * 32 + pp * 16) * 2) + b_off;
            LDSM_X4_T(bh[pp * 2][0], bh[pp * 2][1], bh[pp * 2 + 1][0], bh[pp * 2 + 1][1], rb);
            uint32_t rb2 = base + OFF_BL + (uint32_t)((wn * 32 + pp * 16) * 2) + b_off;
            LDSM_X4_T(bl[pp * 2][0], bl[pp * 2][1], bl[pp * 2 + 1][0], bl[pp * 2 + 1][1], rb2);
        }

        if (ch < 63) stage(cur ^ 1, va0, va1, vw0, vw1);

        // 48 mma
#pragma unroll
        for (int mt = 0; mt < 4; mt++)
#pragma unroll
            for (int nt = 0; nt < 4; nt++) {
                mma16816(acc[mt][nt], ah[mt], bh[nt]);
                mma16816(acc[mt][nt], ah[mt], bl[nt]);
                mma16816(acc[mt][nt], al[mt], bh[nt]);
            }

        __syncthreads();
    }

    // ---- epilogue: direct stores with bias ----
    int lr = lane >> 2, lc = (lane & 3) * 2;
#pragma unroll
    for (int nt = 0; nt < 4; nt++) {
        int col = bn + wn * 32 + nt * 8 + lc;
        float b0 = __ldg(bias + col), b1 = __ldg(bias + col + 1);
#pragma unroll
        for (int mt = 0; mt < 4; mt++) {
            int row = bm + wm * 64 + mt * 16 + lr;
            float2 v0 = make_float2(acc[mt][nt][0] + b0, acc[mt][nt][1] + b1);
            float2 v1 = make_float2(acc[mt][nt][2] + b0, acc[mt][nt][3] + b1);
            *reinterpret_cast<float2*>(C + (size_t)row * 1024 + col) = v0;
            *reinterpret_cast<float2*>(C + (size_t)(row + 8) * 1024 + col) = v1;
        }
    }
}

// ---------------- LayerNorm: one block per row of 1024 ----------------
__global__ __launch_bounds__(256) void ln_kernel(const float* __restrict__ x,
                                                 const float* __restrict__ w,
                                                 const float* __restrict__ b,
                                                 int dst)
{
    float* y = dst ? g_aln : g_tln;
    int row = blockIdx.x;
    int t   = threadIdx.x;
    float4 xv = reinterpret_cast<const float4*>(x)[(size_t)row * 256 + t];
    float s  = xv.x + xv.y + xv.z + xv.w;
    float ss = xv.x * xv.x + xv.y * xv.y + xv.z * xv.z + xv.w * xv.w;
#pragma unroll
    for (int o = 16; o > 0; o >>= 1) {
        s  += __shfl_xor_sync(0xffffffffu, s,  o);
        ss += __shfl_xor_sync(0xffffffffu, ss, o);
    }
    __shared__ float rs[8], rss[8];
    if ((t & 31) == 0) { rs[t >> 5] = s; rss[t >> 5] = ss; }
    __syncthreads();
    float tot = 0.f, tot2 = 0.f;
#pragma unroll
    for (int i = 0; i < 8; i++) { tot += rs[i]; tot2 += rss[i]; }
    float mean = tot  * (1.f / 1024.f);
    float var  = tot2 * (1.f / 1024.f) - mean * mean;
    float rstd = rsqrtf(var + 1e-5f);
    float4 wv = reinterpret_cast<const float4*>(w)[t];
    float4 bv = reinterpret_cast<const float4*>(b)[t];
    float4 o;
    o.x = (xv.x - mean) * rstd * wv.x + bv.x;
    o.y = (xv.y - mean) * rstd * wv.y + bv.y;
    o.z = (xv.z - mean) * rstd * wv.z + bv.z;
    o.w = (xv.w - mean) * rstd * wv.w + bv.w;
    reinterpret_cast<float4*>(y)[(size_t)row * 256 + t] = o;
}

// ---------------- S = sigmoid(Q Kh^T / 8) per (b,h), 64x64 tiles ----------------
__global__ __launch_bounds__(256) void score_kernel()
{
    int bh = blockIdx.z;
    int b  = bh >> 4, h = bh & 15;
    int q0 = blockIdx.y * 64;
    int k0 = blockIdx.x * 64;

    __shared__ __align__(16) float Qs[64][68];
    __shared__ __align__(16) float Ks[64][68];

    int t  = threadIdx.x;
    int tx = t & 15, ty = t >> 4;
    int lr = t >> 2;
    int lq = (t & 3) * 4;

    const float* Qg = g_q + (size_t)(b * NW + q0 + lr) * 1024 + h * 64;
    const float* Kg = g_k + (size_t)(b * NV + k0 + lr) * 1024 + h * 64;
#pragma unroll
    for (int c = 0; c < 4; c++) {
        int col = lq + c * 16;
        float4 q4 = *reinterpret_cast<const float4*>(Qg + col);
        float4 k4 = *reinterpret_cast<const float4*>(Kg + col);
        Qs[col + 0][lr] = q4.x; Qs[col + 1][lr] = q4.y;
        Qs[col + 2][lr] = q4.z; Qs[col + 3][lr] = q4.w;
        Ks[col + 0][lr] = k4.x; Ks[col + 1][lr] = k4.y;
        Ks[col + 2][lr] = k4.z; Ks[col + 3][lr] = k4.w;
    }
    __syncthreads();

    float acc[4][4];
#pragma unroll
    for (int i = 0; i < 4; i++)
#pragma unroll
        for (int j = 0; j < 4; j++) acc[i][j] = 0.f;

#pragma unroll
    for (int d = 0; d < 64; d++) {
        float4 qv = *reinterpret_cast<const float4*>(&Qs[d][ty * 4]);
        float4 kv = *reinterpret_cast<const float4*>(&Ks[d][tx * 4]);
        float qa[4] = {qv.x, qv.y, qv.z, qv.w};
        float ka[4] = {kv.x, kv.y, kv.z, kv.w};
#pragma unroll
        for (int i = 0; i < 4; i++)
#pragma unroll
            for (int j = 0; j < 4; j++)
                acc[i][j] += qa[i] * ka[j];
    }

    float* Ap = g_attn + ((size_t)bh * NW + q0 + ty * 4) * 1024 + k0 + tx * 4;
#pragma unroll
    for (int i = 0; i < 4; i++) {
        float4 o;
        o.x = 1.f / (1.f + __expf(-0.125f * acc[i][0]));
        o.y = 1.f / (1.f + __expf(-0.125f * acc[i][1]));
        o.z = 1.f / (1.f + __expf(-0.125f * acc[i][2]));
        o.w = 1.f / (1.f + __expf(-0.125f * acc[i][3]));
        *reinterpret_cast<float4*>(Ap + (size_t)i * 1024) = o;
    }
}

// ---------------- out[b,q,h,:] = S @ Vh ----------------
__global__ __launch_bounds__(256) void av_kernel(float* __restrict__ out)
{
    int bh = blockIdx.y;
    int b  = bh >> 4, h = bh & 15;
    int q0 = blockIdx.x * 64;

    __shared__ __align__(16) float Ss[16][68];
    __shared__ __align__(16) float Vs[16][64];

    int t  = threadIdx.x;
    int tx = t & 15, ty = t >> 4;
    int sr = t >> 2,  sc = (t & 3) * 4;
    int vr = t >> 4,  vc = (t & 15) * 4;

    const float* Sg = g_attn + ((size_t)bh * NW + q0) * 1024;
    const float* Vg = g_v + (size_t)(b * NV) * 1024 + h * 64;

    float acc[4][4];
#pragma unroll
    for (int i = 0; i < 4; i++)
#pragma unroll
        for (int j = 0; j < 4; j++) acc[i][j] = 0.f;

    for (int kc = 0; kc < 1024; kc += 16) {
        float4 s4 = *reinterpret_cast<const float4*>(Sg + (size_t)sr * 1024 + kc + sc);
        float4 v4 = *reinterpret_cast<const float4*>(Vg + (size_t)(kc + vr) * 1024 + vc);
        __syncthreads();
        Ss[sc + 0][sr] = s4.x; Ss[sc + 1][sr] = s4.y;
        Ss[sc + 2][sr] = s4.z; Ss[sc + 3][sr] = s4.w;
        *reinterpret_cast<float4*>(&Vs[vr][vc]) = v4;
        __syncthreads();
#pragma unroll
        for (int k = 0; k < 16; k++) {
            float4 sv = *reinterpret_cast<const float4*>(&Ss[k][ty * 4]);
            float4 vv = *reinterpret_cast<const float4*>(&Vs[k][tx * 4]);
            float sa[4] = {sv.x, sv.y, sv.z, sv.w};
            float va[4] = {vv.x, vv.y, vv.z, vv.w};
#pragma unroll
            for (int i = 0; i < 4; i++)
#pragma unroll
                for (int j = 0; j < 4; j++)
                    acc[i][j] += sa[i] * va[j];
        }
    }

    float* Op = out + (size_t)(b * NW + q0 + ty * 4) * 1024 + h * 64 + tx * 4;
#pragma unroll
    for (int i = 0; i < 4; i++) {
        float4 o;
        o.x = acc[i][0]; o.y = acc[i][1]; o.z = acc[i][2]; o.w = acc[i][3];
        *reinterpret_cast<float4*>(Op + (size_t)i * 1024) = o;
    }
}

// ---------------- attn.mean over heads ----------------
__global__ __launch_bounds__(256) void mean_kernel(float* __restrict__ mn)
{
    size_t idx4 = (size_t)blockIdx.x * 256 + threadIdx.x;
    size_t base = idx4 * 4;
    size_t b    = base >> 19;
    size_t qk   = base & 524287;
    const float* p = g_attn + b * (size_t)(NHEAD * 524288) + qk;
    float4 s = make_float4(0.f, 0.f, 0.f, 0.f);
#pragma unroll
    for (int h = 0; h < NHEAD; h++) {
        float4 v = *reinterpret_cast<const float4*>(p + (size_t)h * 524288);
        s.x += v.x; s.y += v.y; s.z += v.z; s.w += v.w;
    }
    s.x *= 0.0625f; s.y *= 0.0625f; s.z *= 0.0625f; s.w *= 0.0625f;
    *reinterpret_cast<float4*>(mn + base) = s;
}

// ---------------- launch ----------------
extern "C" void kernel_launch(void* const* d_in, const int* in_sizes, int n_in,
                              void* d_out, int out_size)
{
    (void)in_sizes; (void)n_in; (void)out_size;
    const float* text = (const float*)d_in[0];
    const float* av   = (const float*)d_in[1];
    const float* tn_w = (const float*)d_in[2];
    const float* tn_b = (const float*)d_in[3];
    const float* an_w = (const float*)d_in[4];
    const float* an_b = (const float*)d_in[5];
    const float* Wq   = (const float*)d_in[6];
    const float* bq   = (const float*)d_in[7];
    const float* Wk   = (const float*)d_in[8];
    const float* bk   = (const float*)d_in[9];
    const float* Wv   = (const float*)d_in[10];
    const float* bv   = (const float*)d_in[11];

    float* out   = (float*)d_out;
    float* amean = out + (size_t)BS * NW * D_MODEL;

    ln_kernel<<<BS * NW, 256>>>(text, tn_w, tn_b, 0);
    ln_kernel<<<BS * NV, 256>>>(av, an_w, an_b, 1);

    gemm_tc<<<dim3(BS * NW / 128, 8), 256>>>(0, Wq, bq, 0);
    gemm_tc<<<dim3(BS * NV / 128, 8), 256>>>(1, Wk, bk, 1);
    gemm_tc<<<dim3(BS * NV / 128, 8), 256>>>(1, Wv, bv, 2);

    score_kernel<<<dim3(NV / 64, NW / 64, BS * NHEAD), 256>>>();
    av_kernel<<<dim3(NW / 64, BS * NHEAD), 256>>>(out);
    mean_kernel<<<(BS * NW * NV) / (4 * 256), 256>>>(amean);
}

// round 4
// speedup vs baseline: 1.7720x; 1.2691x over previous
#include <cuda_runtime.h>
#include <cuda_bf16.h>
#include <cstdint>

typedef __nv_bfloat16 bf16;

#define BS 8
#define NW 512
#define NV 1024

// ---------------- bf16 hi/lo planes (allocation-free scratch) ----------------
__device__ bf16 g_tah[BS*NW*1024], g_tal[BS*NW*1024];      // LN(text)
__device__ bf16 g_aah[BS*NV*1024], g_aal[BS*NV*1024];      // LN(av)
__device__ bf16 g_wth[3][1024*1024], g_wtl[3][1024*1024];  // W^T [k][n]
__device__ bf16 g_qh[BS*NW*1024],  g_ql[BS*NW*1024];
__device__ bf16 g_kh[BS*NV*1024],  g_kl[BS*NV*1024];
__device__ bf16 g_vh[BS*NV*1024],  g_vl[BS*NV*1024];
__device__ bf16 g_sh[(size_t)BS*16*NW*NV], g_sl[(size_t)BS*16*NW*NV];  // sigmoid scores

// ---------------- helpers ----------------
__device__ __forceinline__ uint32_t smem_to_u32(const void* p) {
    uint32_t a;
    asm("{ .reg .u64 t; cvta.to.shared.u64 t, %1; cvt.u32.u64 %0, t; }" : "=r"(a) : "l"(p));
    return a;
}
__device__ __forceinline__ void split_pack(float x0, float x1, uint32_t& hi, uint32_t& lo) {
    __nv_bfloat16 h0 = __float2bfloat16(x0), h1 = __float2bfloat16(x1);
    float r0 = x0 - __bfloat162float(h0), r1 = x1 - __bfloat162float(h1);
    __nv_bfloat16 l0 = __float2bfloat16(r0), l1 = __float2bfloat16(r1);
    hi = ((uint32_t)__bfloat16_as_ushort(h1) << 16) | __bfloat16_as_ushort(h0);
    lo = ((uint32_t)__bfloat16_as_ushort(l1) << 16) | __bfloat16_as_ushort(l0);
}
__device__ __forceinline__ float bflo(uint32_t u) { return __uint_as_float(u << 16); }
__device__ __forceinline__ float bfhi(uint32_t u) { return __uint_as_float(u & 0xFFFF0000u); }

#define LDSM_X4(r0, r1, r2, r3, addr) \
    asm volatile("ldmatrix.sync.aligned.m8n8.x4.shared.b16 {%0,%1,%2,%3}, [%4];" \
        : "=r"(r0), "=r"(r1), "=r"(r2), "=r"(r3) : "r"(addr))
#define LDSM_X4_T(r0, r1, r2, r3, addr) \
    asm volatile("ldmatrix.sync.aligned.m8n8.x4.trans.shared.b16 {%0,%1,%2,%3}, [%4];" \
        : "=r"(r0), "=r"(r1), "=r"(r2), "=r"(r3) : "r"(addr))

__device__ __forceinline__ void mma16816(float* c, const uint32_t* a, const uint32_t* b) {
    asm volatile(
        "mma.sync.aligned.m16n8k16.row.col.f32.bf16.bf16.f32 "
        "{%0,%1,%2,%3}, {%4,%5,%6,%7}, {%8,%9}, {%0,%1,%2,%3};"
        : "+f"(c[0]), "+f"(c[1]), "+f"(c[2]), "+f"(c[3])
        : "r"(a[0]), "r"(a[1]), "r"(a[2]), "r"(a[3]), "r"(b[0]), "r"(b[1]));
}

#define CP16(dst, src) \
    asm volatile("cp.async.cg.shared.global [%0], [%1], 16;" :: "r"((uint32_t)(dst)), "l"(src) : "memory")
#define CP_COMMIT() asm volatile("cp.async.commit_group;" ::: "memory")
#define CP_WAIT(n)  asm volatile("cp.async.wait_group %0;" :: "n"(n) : "memory")

// ---------------- LayerNorm -> bf16 hi/lo planes ----------------
__global__ __launch_bounds__(256) void ln_split(const float* __restrict__ x,
                                                const float* __restrict__ w,
                                                const float* __restrict__ b,
                                                int dst)
{
    bf16* yh = dst ? g_aah : g_tah;
    bf16* yl = dst ? g_aal : g_tal;
    int row = blockIdx.x, t = threadIdx.x;
    float4 xv = reinterpret_cast<const float4*>(x)[(size_t)row * 256 + t];
    float s  = xv.x + xv.y + xv.z + xv.w;
    float ss = xv.x*xv.x + xv.y*xv.y + xv.z*xv.z + xv.w*xv.w;
#pragma unroll
    for (int o = 16; o > 0; o >>= 1) {
        s  += __shfl_xor_sync(0xffffffffu, s,  o);
        ss += __shfl_xor_sync(0xffffffffu, ss, o);
    }
    __shared__ float rs[8], rss[8];
    if ((t & 31) == 0) { rs[t >> 5] = s; rss[t >> 5] = ss; }
    __syncthreads();
    float tot = 0.f, tot2 = 0.f;
#pragma unroll
    for (int i = 0; i < 8; i++) { tot += rs[i]; tot2 += rss[i]; }
    float mean = tot * (1.f / 1024.f);
    float var  = tot2 * (1.f / 1024.f) - mean * mean;
    float rstd = rsqrtf(var + 1e-5f);
    float4 wv = reinterpret_cast<const float4*>(w)[t];
    float4 bv = reinterpret_cast<const float4*>(b)[t];
    float o0 = (xv.x - mean) * rstd * wv.x + bv.x;
    float o1 = (xv.y - mean) * rstd * wv.y + bv.y;
    float o2 = (xv.z - mean) * rstd * wv.z + bv.z;
    float o3 = (xv.w - mean) * rstd * wv.w + bv.w;
    uint32_t h0, l0, h1, l1;
    split_pack(o0, o1, h0, l0);
    split_pack(o2, o3, h1, l1);
    *reinterpret_cast<uint2*>(reinterpret_cast<char*>(yh) + (size_t)row * 2048 + t * 8) = make_uint2(h0, h1);
    *reinterpret_cast<uint2*>(reinterpret_cast<char*>(yl) + (size_t)row * 2048 + t * 8) = make_uint2(l0, l1);
}

// ---------------- W[n][k] -> W^T[k][n] hi/lo ----------------
__global__ void wsplit(const float* __restrict__ Wq,
                       const float* __restrict__ Wk,
                       const float* __restrict__ Wv)
{
    int wsel = blockIdx.z;
    const float* W = (wsel == 0) ? Wq : (wsel == 1) ? Wk : Wv;
    bf16* th = g_wth[wsel];
    bf16* tl = g_wtl[wsel];
    __shared__ float tile[32][33];
    int k = blockIdx.x * 32 + threadIdx.x;
    int n0 = blockIdx.y * 32;
#pragma unroll
    for (int i = threadIdx.y; i < 32; i += 8)
        tile[i][threadIdx.x] = W[(size_t)(n0 + i) * 1024 + k];
    __syncthreads();
#pragma unroll
    for (int i = threadIdx.y; i < 32; i += 8) {
        float v = tile[threadIdx.x][i];               // = W[n0+tx][bx*32+i]
        __nv_bfloat16 h = __float2bfloat16(v);
        __nv_bfloat16 l = __float2bfloat16(v - __bfloat162float(h));
        size_t idx = (size_t)(blockIdx.x * 32 + i) * 1024 + n0 + threadIdx.x;
        th[idx] = h;
        tl[idx] = l;
    }
}

// ---------------- projection GEMM: C = A @ W^T + bias -> hi/lo planes ----------------
// smem stage: A-hi [128][48B], A-lo, B-hi [16][272B], B-lo
#define G_AHOFF 0
#define G_ALOFF 6144
#define G_BHOFF 12288
#define G_BLOFF 16640
#define G_STAGE 20992

__global__ __launch_bounds__(256, 1) void gemm_tc(int src, int dst,
                                                  const float* __restrict__ bias)
{
    extern __shared__ __align__(16) uint8_t smg[];
    const bf16* Ah = src ? g_aah : g_tah;
    const bf16* Al = src ? g_aal : g_tal;
    const bf16* Bh = g_wth[dst];
    const bf16* Bl = g_wtl[dst];
    bf16* Ch = (dst == 0) ? g_qh : (dst == 1) ? g_kh : g_vh;
    bf16* Cl = (dst == 0) ? g_ql : (dst == 1) ? g_kl : g_vl;

    int t = threadIdx.x, lane = t & 31, warp = t >> 5;
    int wm = warp >> 2, wn = warp & 3;
    int bm = blockIdx.x * 128, bn = blockIdx.y * 128;
    uint32_t smb = smem_to_u32(smg);

    int arow = t >> 1, aseg = t & 1;
    int brow = t >> 4, bseg = t & 15;
    const bf16* agh = Ah + (size_t)(bm + arow) * 1024 + aseg * 8;
    const bf16* agl = Al + (size_t)(bm + arow) * 1024 + aseg * 8;
    const bf16* bgh = Bh + (size_t)brow * 1024 + bn + bseg * 8;
    const bf16* bgl = Bl + (size_t)brow * 1024 + bn + bseg * 8;
    uint32_t a_dst = arow * 48 + aseg * 16;
    uint32_t b_dst = brow * 272 + bseg * 16;

    auto issue = [&](int ch) {
        uint32_t base = smb + (uint32_t)((ch & 3) * G_STAGE);
        CP16(base + G_AHOFF + a_dst, agh + ch * 16);
        CP16(base + G_ALOFF + a_dst, agl + ch * 16);
        CP16(base + G_BHOFF + b_dst, bgh + (size_t)ch * 16 * 1024);
        CP16(base + G_BLOFF + b_dst, bgl + (size_t)ch * 16 * 1024);
    };

    float acc[4][4][4];
#pragma unroll
    for (int i = 0; i < 4; i++)
#pragma unroll
        for (int j = 0; j < 4; j++)
#pragma unroll
            for (int e = 0; e < 4; e++) acc[i][j][e] = 0.f;

    issue(0); CP_COMMIT();
    issue(1); CP_COMMIT();
    issue(2); CP_COMMIT();

    uint32_t a_off = (lane & 15) * 48 + (lane >> 4) * 16;
    uint32_t b_off = ((lane & 7) + ((lane >> 3) & 1) * 8) * 272 + (lane >> 4) * 16;

    for (int ch = 0; ch < 64; ch++) {
        CP_WAIT(2);
        __syncthreads();
        if (ch + 3 < 64) issue(ch + 3);
        CP_COMMIT();

        uint32_t base = smb + (uint32_t)((ch & 3) * G_STAGE);
        uint32_t ah[4][4], al[4][4], bh2[4][2], bl2[4][2];
#pragma unroll
        for (int mt = 0; mt < 4; mt++) {
            uint32_t r = base + G_AHOFF + (uint32_t)((wm * 64 + mt * 16) * 48) + a_off;
            LDSM_X4(ah[mt][0], ah[mt][1], ah[mt][2], ah[mt][3], r);
            uint32_t rl = base + G_ALOFF + (uint32_t)((wm * 64 + mt * 16) * 48) + a_off;
            LDSM_X4(al[mt][0], al[mt][1], al[mt][2], al[mt][3], rl);
        }
#pragma unroll
        for (int pp = 0; pp < 2; pp++) {
            uint32_t r = base + G_BHOFF + (uint32_t)((wn * 32 + pp * 16) * 2) + b_off;
            LDSM_X4_T(bh2[pp*2][0], bh2[pp*2][1], bh2[pp*2+1][0], bh2[pp*2+1][1], r);
            uint32_t rl = base + G_BLOFF + (uint32_t)((wn * 32 + pp * 16) * 2) + b_off;
            LDSM_X4_T(bl2[pp*2][0], bl2[pp*2][1], bl2[pp*2+1][0], bl2[pp*2+1][1], rl);
        }
#pragma unroll
        for (int mt = 0; mt < 4; mt++)
#pragma unroll
            for (int nt = 0; nt < 4; nt++) {
                mma16816(acc[mt][nt], ah[mt], bh2[nt]);
                mma16816(acc[mt][nt], ah[mt], bl2[nt]);
                mma16816(acc[mt][nt], al[mt], bh2[nt]);
            }
    }

    // epilogue: +bias, split to hi/lo bf16
    int lr = lane >> 2, lc = (lane & 3) * 2;
#pragma unroll
    for (int nt = 0; nt < 4; nt++) {
        int col = bn + wn * 32 + nt * 8 + lc;
        float b0 = __ldg(bias + col), b1 = __ldg(bias + col + 1);
#pragma unroll
        for (int mt = 0; mt < 4; mt++) {
            int row = bm + wm * 64 + mt * 16 + lr;
            uint32_t h01, l01;
            split_pack(acc[mt][nt][0] + b0, acc[mt][nt][1] + b1, h01, l01);
            *reinterpret_cast<uint32_t*>(reinterpret_cast<char*>(Ch) + ((size_t)row * 1024 + col) * 2) = h01;
            *reinterpret_cast<uint32_t*>(reinterpret_cast<char*>(Cl) + ((size_t)row * 1024 + col) * 2) = l01;
            split_pack(acc[mt][nt][2] + b0, acc[mt][nt][3] + b1, h01, l01);
            *reinterpret_cast<uint32_t*>(reinterpret_cast<char*>(Ch) + ((size_t)(row + 8) * 1024 + col) * 2) = h01;
            *reinterpret_cast<uint32_t*>(reinterpret_cast<char*>(Cl) + ((size_t)(row + 8) * 1024 + col) * 2) = l01;
        }
    }
}

// ---------------- score: S = sigmoid(Q K^T / 8) -> hi/lo planes ----------------
// smem: Q-hi [128][144B], Q-lo, K-hi [128][144B], K-lo (one shot, K-dim=64)
#define S_QH 0
#define S_QL 18432
#define S_KH 36864
#define S_KL 55296

__global__ __launch_bounds__(256, 1) void score_tc()
{
    extern __shared__ __align__(16) uint8_t smg[];
    int bh = blockIdx.z, b = bh >> 4, h = bh & 15;
    int q0 = blockIdx.y * 128, k0 = blockIdx.x * 128;
    int t = threadIdx.x, lane = t & 31, warp = t >> 5;
    int wm = warp >> 2, wn = warp & 3;
    uint32_t smb = smem_to_u32(smg);

#pragma unroll
    for (int i = 0; i < 4; i++) {
        int idx = t + i * 256;
        int row = idx >> 3, seg = idx & 7;
        uint32_t d = (uint32_t)(row * 144 + seg * 16);
        CP16(smb + S_QH + d, g_qh + (size_t)(b * 512 + q0 + row) * 1024 + h * 64 + seg * 8);
        CP16(smb + S_QL + d, g_ql + (size_t)(b * 512 + q0 + row) * 1024 + h * 64 + seg * 8);
        CP16(smb + S_KH + d, g_kh + (size_t)(b * 1024 + k0 + row) * 1024 + h * 64 + seg * 8);
        CP16(smb + S_KL + d, g_kl + (size_t)(b * 1024 + k0 + row) * 1024 + h * 64 + seg * 8);
    }
    CP_COMMIT();
    CP_WAIT(0);
    __syncthreads();

    uint32_t a_off = (lane & 15) * 144 + (lane >> 4) * 16;
    uint32_t b_off = ((lane & 7) + ((lane >> 4) & 1) * 8) * 144 + ((lane >> 3) & 1) * 16;

    float acc[4][4][4];
#pragma unroll
    for (int i = 0; i < 4; i++)
#pragma unroll
        for (int j = 0; j < 4; j++)
#pragma unroll
            for (int e = 0; e < 4; e++) acc[i][j][e] = 0.f;

#pragma unroll
    for (int kc = 0; kc < 4; kc++) {
        uint32_t ah[4][4], al[4][4], bh2[4][2], bl2[4][2];
#pragma unroll
        for (int mt = 0; mt < 4; mt++) {
            uint32_t r = smb + S_QH + (uint32_t)((wm * 64 + mt * 16) * 144) + kc * 32 + a_off;
            LDSM_X4(ah[mt][0], ah[mt][1], ah[mt][2], ah[mt][3], r);
            uint32_t rl = smb + S_QL + (uint32_t)((wm * 64 + mt * 16) * 144) + kc * 32 + a_off;
            LDSM_X4(al[mt][0], al[mt][1], al[mt][2], al[mt][3], rl);
        }
#pragma unroll
        for (int pp = 0; pp < 2; pp++) {
            uint32_t r = smb + S_KH + (uint32_t)((wn * 32 + pp * 16) * 144) + kc * 32 + b_off;
            LDSM_X4(bh2[pp*2][0], bh2[pp*2][1], bh2[pp*2+1][0], bh2[pp*2+1][1], r);
            uint32_t rl = smb + S_KL + (uint32_t)((wn * 32 + pp * 16) * 144) + kc * 32 + b_off;
            LDSM_X4(bl2[pp*2][0], bl2[pp*2][1], bl2[pp*2+1][0], bl2[pp*2+1][1], rl);
        }
#pragma unroll
        for (int mt = 0; mt < 4; mt++)
#pragma unroll
            for (int nt = 0; nt < 4; nt++) {
                mma16816(acc[mt][nt], ah[mt], bh2[nt]);
                mma16816(acc[mt][nt], ah[mt], bl2[nt]);
                mma16816(acc[mt][nt], al[mt], bh2[nt]);
            }
    }

    // sigmoid + split + store
    int lr = lane >> 2, lc = (lane & 3) * 2;
    size_t splane = (size_t)bh * 524288;
#pragma unroll
    for (int nt = 0; nt < 4; nt++) {
        int col = k0 + wn * 32 + nt * 8 + lc;
#pragma unroll
        for (int mt = 0; mt < 4; mt++) {
            int row = q0 + wm * 64 + mt * 16 + lr;
            float s0 = 1.f / (1.f + __expf(-0.125f * acc[mt][nt][0]));
            float s1 = 1.f / (1.f + __expf(-0.125f * acc[mt][nt][1]));
            float s2 = 1.f / (1.f + __expf(-0.125f * acc[mt][nt][2]));
            float s3 = 1.f / (1.f + __expf(-0.125f * acc[mt][nt][3]));
            uint32_t h01, l01;
            split_pack(s0, s1, h01, l01);
            *reinterpret_cast<uint32_t*>(reinterpret_cast<char*>(g_sh) + (splane + (size_t)row * 1024 + col) * 2) = h01;
            *reinterpret_cast<uint32_t*>(reinterpret_cast<char*>(g_sl) + (splane + (size_t)row * 1024 + col) * 2) = l01;
            split_pack(s2, s3, h01, l01);
            *reinterpret_cast<uint32_t*>(reinterpret_cast<char*>(g_sh) + (splane + (size_t)(row + 8) * 1024 + col) * 2) = h01;
            *reinterpret_cast<uint32_t*>(reinterpret_cast<char*>(g_sl) + (splane + (size_t)(row + 8) * 1024 + col) * 2) = l01;
        }
    }
}

// ---------------- AV: out = S @ V ----------------
// smem stage: S-hi [128][48B], S-lo, V-hi [16][144B], V-lo
#define A_SH 0
#define A_SL 6144
#define A_VH 12288
#define A_VL 14592
#define A_STAGE 16896

__global__ __launch_bounds__(256, 2) void av_tc(float* __restrict__ out)
{
    extern __shared__ __align__(16) uint8_t smg[];
    int bh = blockIdx.y, b = bh >> 4, h = bh & 15;
    int q0 = blockIdx.x * 128;
    int t = threadIdx.x, lane = t & 31, warp = t >> 5;
    int wm = warp >> 1, wn = warp & 1;
    uint32_t smb = smem_to_u32(smg);

    int srow = t >> 1, sseg = t & 1;
    uint32_t s_dst = srow * 48 + sseg * 16;
    const bf16* sgh = g_sh + ((size_t)bh * 512 + q0 + srow) * 1024 + sseg * 8;
    const bf16* sgl = g_sl + ((size_t)bh * 512 + q0 + srow) * 1024 + sseg * 8;
    int vrow = (t & 127) >> 3, vseg = t & 7;
    uint32_t v_dst = (t < 128 ? A_VH : A_VL) + vrow * 144 + vseg * 16;
    const bf16* vg = (t < 128 ? g_vh : g_vl) + (size_t)(b * 1024 + vrow) * 1024 + h * 64 + vseg * 8;

    auto issue = [&](int ch) {
        uint32_t base = smb + (uint32_t)((ch & 3) * A_STAGE);
        CP16(base + A_SH + s_dst, sgh + ch * 16);
        CP16(base + A_SL + s_dst, sgl + ch * 16);
        CP16(base + v_dst, vg + (size_t)ch * 16 * 1024);
    };

    float acc[2][4][4];
#pragma unroll
    for (int i = 0; i < 2; i++)
#pragma unroll
        for (int j = 0; j < 4; j++)
#pragma unroll
            for (int e = 0; e < 4; e++) acc[i][j][e] = 0.f;

    issue(0); CP_COMMIT();
    issue(1); CP_COMMIT();
    issue(2); CP_COMMIT();

    uint32_t a_off = (lane & 15) * 48 + (lane >> 4) * 16;
    uint32_t b_off = ((lane & 7) + ((lane >> 3) & 1) * 8) * 144 + (lane >> 4) * 16;

    for (int ch = 0; ch < 64; ch++) {
        CP_WAIT(2);
        __syncthreads();
        if (ch + 3 < 64) issue(ch + 3);
        CP_COMMIT();

        uint32_t base = smb + (uint32_t)((ch & 3) * A_STAGE);
        uint32_t ah[2][4], al[2][4], bh2[4][2], bl2[4][2];
#pragma unroll
        for (int mt = 0; mt < 2; mt++) {
            uint32_t r = base + A_SH + (uint32_t)((wm * 32 + mt * 16) * 48) + a_off;
            LDSM_X4(ah[mt][0], ah[mt][1], ah[mt][2], ah[mt][3], r);
            uint32_t rl = base + A_SL + (uint32_t)((wm * 32 + mt * 16) * 48) + a_off;
            LDSM_X4(al[mt][0], al[mt][1], al[mt][2], al[mt][3], rl);
        }
#pragma unroll
        for (int pp = 0; pp < 2; pp++) {
            uint32_t r = base + A_VH + (uint32_t)((wn * 32 + pp * 16) * 2) + b_off;
            LDSM_X4_T(bh2[pp*2][0], bh2[pp*2][1], bh2[pp*2+1][0], bh2[pp*2+1][1], r);
            uint32_t rl = base + A_VL + (uint32_t)((wn * 32 + pp * 16) * 2) + b_off;
            LDSM_X4_T(bl2[pp*2][0], bl2[pp*2][1], bl2[pp*2+1][0], bl2[pp*2+1][1], rl);
        }
#pragma unroll
        for (int mt = 0; mt < 2; mt++)
#pragma unroll
            for (int nt = 0; nt < 4; nt++) {
                mma16816(acc[mt][nt], ah[mt], bh2[nt]);
                mma16816(acc[mt][nt], ah[mt], bl2[nt]);
                mma16816(acc[mt][nt], al[mt], bh2[nt]);
            }
    }

    int lr = lane >> 2, lc = (lane & 3) * 2;
#pragma unroll
    for (int nt = 0; nt < 4; nt++) {
        int col = h * 64 + wn * 32 + nt * 8 + lc;
#pragma unroll
        for (int mt = 0; mt < 2; mt++) {
            int row = b * 512 + q0 + wm * 32 + mt * 16 + lr;
            *reinterpret_cast<float2*>(out + (size_t)row * 1024 + col) =
                make_float2(acc[mt][nt][0], acc[mt][nt][1]);
            *reinterpret_cast<float2*>(out + (size_t)(row + 8) * 1024 + col) =
                make_float2(acc[mt][nt][2], acc[mt][nt][3]);
        }
    }
}

// ---------------- attn.mean over heads (hi+lo reconstruct) ----------------
__global__ __launch_bounds__(256) void mean_kernel(float* __restrict__ mn)
{
    size_t e = ((size_t)blockIdx.x * 256 + threadIdx.x) * 8;
    size_t b = e >> 19;
    size_t qk = e & 524287;
    float s[8];
#pragma unroll
    for (int i = 0; i < 8; i++) s[i] = 0.f;
#pragma unroll
    for (int hh = 0; hh < 16; hh++) {
        size_t off = ((b * 16 + hh) * 524288 + qk) * 2;   // bytes
        uint4 vh = *reinterpret_cast<const uint4*>(reinterpret_cast<const char*>(g_sh) + off);
        uint4 vl = *reinterpret_cast<const uint4*>(reinterpret_cast<const char*>(g_sl) + off);
        s[0] += bflo(vh.x) + bflo(vl.x);  s[1] += bfhi(vh.x) + bfhi(vl.x);
        s[2] += bflo(vh.y) + bflo(vl.y);  s[3] += bfhi(vh.y) + bfhi(vl.y);
        s[4] += bflo(vh.z) + bflo(vl.z);  s[5] += bfhi(vh.z) + bfhi(vl.z);
        s[6] += bflo(vh.w) + bflo(vl.w);  s[7] += bfhi(vh.w) + bfhi(vl.w);
    }
    float4 o0 = make_float4(s[0] * 0.0625f, s[1] * 0.0625f, s[2] * 0.0625f, s[3] * 0.0625f);
    float4 o1 = make_float4(s[4] * 0.0625f, s[5] * 0.0625f, s[6] * 0.0625f, s[7] * 0.0625f);
    *reinterpret_cast<float4*>(mn + e) = o0;
    *reinterpret_cast<float4*>(mn + e + 4) = o1;
}

// ---------------- launch ----------------
extern "C" void kernel_launch(void* const* d_in, const int* in_sizes, int n_in,
                              void* d_out, int out_size)
{
    (void)in_sizes; (void)n_in; (void)out_size;
    const float* text = (const float*)d_in[0];
    const float* av   = (const float*)d_in[1];
    const float* tn_w = (const float*)d_in[2];
    const float* tn_b = (const float*)d_in[3];
    const float* an_w = (const float*)d_in[4];
    const float* an_b = (const float*)d_in[5];
    const float* Wq   = (const float*)d_in[6];
    const float* bq   = (const float*)d_in[7];
    const float* Wk   = (const float*)d_in[8];
    const float* bk   = (const float*)d_in[9];
    const float* Wv   = (const float*)d_in[10];
    const float* bv   = (const float*)d_in[11];

    float* out   = (float*)d_out;
    float* amean = out + (size_t)BS * NW * 1024;

    static int attr_done = 0;
    if (!attr_done) {
        cudaFuncSetAttribute(gemm_tc,  cudaFuncAttributeMaxDynamicSharedMemorySize, 4 * G_STAGE);
        cudaFuncSetAttribute(score_tc, cudaFuncAttributeMaxDynamicSharedMemorySize, 73728);
        cudaFuncSetAttribute(av_tc,    cudaFuncAttributeMaxDynamicSharedMemorySize, 4 * A_STAGE);
        attr_done = 1;
    }

    ln_split<<<BS * NW, 256>>>(text, tn_w, tn_b, 0);
    ln_split<<<BS * NV, 256>>>(av, an_w, an_b, 1);
    wsplit<<<dim3(32, 32, 3), dim3(32, 8)>>>(Wq, Wk, Wv);

    gemm_tc<<<dim3(32, 8), 256, 4 * G_STAGE>>>(0, 0, bq);
    gemm_tc<<<dim3(64, 8), 256, 4 * G_STAGE>>>(1, 1, bk);
    gemm_tc<<<dim3(64, 8), 256, 4 * G_STAGE>>>(1, 2, bv);

    score_tc<<<dim3(8, 4, 128), 256, 73728>>>();
    av_tc<<<dim3(4, 128), 256, 4 * A_STAGE>>>(out);
    mean_kernel<<<2048, 256>>>(amean);
}

// round 5
// speedup vs baseline: 1.7872x; 1.0086x over previous
#include <cuda_runtime.h>
#include <cuda_bf16.h>
#include <cstdint>

typedef __nv_bfloat16 bf16;

#define BS 8
#define NW 512
#define NV 1024

// ---------------- bf16 hi/lo planes (allocation-free scratch) ----------------
__device__ bf16 g_tah[BS*NW*1024], g_tal[BS*NW*1024];      // LN(text)
__device__ bf16 g_aah[BS*NV*1024], g_aal[BS*NV*1024];      // LN(av)
__device__ bf16 g_wth[3][1024*1024], g_wtl[3][1024*1024];  // W^T [k][n]
__device__ bf16 g_qh[BS*NW*1024],  g_ql[BS*NW*1024];
__device__ bf16 g_kh[BS*NV*1024],  g_kl[BS*NV*1024];
__device__ bf16 g_vh[BS*NV*1024],  g_vl[BS*NV*1024];
__device__ bf16 g_sh[(size_t)BS*16*NW*NV], g_sl[(size_t)BS*16*NW*NV];  // sigmoid scores

// ---------------- helpers ----------------
__device__ __forceinline__ uint32_t smem_to_u32(const void* p) {
    uint32_t a;
    asm("{ .reg .u64 t; cvta.to.shared.u64 t, %1; cvt.u32.u64 %0, t; }" : "=r"(a) : "l"(p));
    return a;
}
__device__ __forceinline__ void split_pack(float x0, float x1, uint32_t& hi, uint32_t& lo) {
    __nv_bfloat16 h0 = __float2bfloat16(x0), h1 = __float2bfloat16(x1);
    float r0 = x0 - __bfloat162float(h0), r1 = x1 - __bfloat162float(h1);
    __nv_bfloat16 l0 = __float2bfloat16(r0), l1 = __float2bfloat16(r1);
    hi = ((uint32_t)__bfloat16_as_ushort(h1) << 16) | __bfloat16_as_ushort(h0);
    lo = ((uint32_t)__bfloat16_as_ushort(l1) << 16) | __bfloat16_as_ushort(l0);
}

#define LDSM_X4(r0, r1, r2, r3, addr) \
    asm volatile("ldmatrix.sync.aligned.m8n8.x4.shared.b16 {%0,%1,%2,%3}, [%4];" \
        : "=r"(r0), "=r"(r1), "=r"(r2), "=r"(r3) : "r"(addr))
#define LDSM_X4_T(r0, r1, r2, r3, addr) \
    asm volatile("ldmatrix.sync.aligned.m8n8.x4.trans.shared.b16 {%0,%1,%2,%3}, [%4];" \
        : "=r"(r0), "=r"(r1), "=r"(r2), "=r"(r3) : "r"(addr))

__device__ __forceinline__ void mma16816(float* c, const uint32_t* a, const uint32_t* b) {
    asm volatile(
        "mma.sync.aligned.m16n8k16.row.col.f32.bf16.bf16.f32 "
        "{%0,%1,%2,%3}, {%4,%5,%6,%7}, {%8,%9}, {%0,%1,%2,%3};"
        : "+f"(c[0]), "+f"(c[1]), "+f"(c[2]), "+f"(c[3])
        : "r"(a[0]), "r"(a[1]), "r"(a[2]), "r"(a[3]), "r"(b[0]), "r"(b[1]));
}

#define CP16(dst, src) \
    asm volatile("cp.async.cg.shared.global [%0], [%1], 16;" :: "r"((uint32_t)(dst)), "l"(src) : "memory")
#define CP_COMMIT() asm volatile("cp.async.commit_group;" ::: "memory")
#define CP_WAIT(n)  asm volatile("cp.async.wait_group %0;" :: "n"(n) : "memory")

// ---------------- LayerNorm -> bf16 hi/lo planes ----------------
__global__ __launch_bounds__(256) void ln_split(const float* __restrict__ x,
                                                const float* __restrict__ w,
                                                const float* __restrict__ b,
                                                int dst)
{
    bf16* yh = dst ? g_aah : g_tah;
    bf16* yl = dst ? g_aal : g_tal;
    int row = blockIdx.x, t = threadIdx.x;
    float4 xv = reinterpret_cast<const float4*>(x)[(size_t)row * 256 + t];
    float s  = xv.x + xv.y + xv.z + xv.w;
    float ss = xv.x*xv.x + xv.y*xv.y + xv.z*xv.z + xv.w*xv.w;
#pragma unroll
    for (int o = 16; o > 0; o >>= 1) {
        s  += __shfl_xor_sync(0xffffffffu, s,  o);
        ss += __shfl_xor_sync(0xffffffffu, ss, o);
    }
    __shared__ float rs[8], rss[8];
    if ((t & 31) == 0) { rs[t >> 5] = s; rss[t >> 5] = ss; }
    __syncthreads();
    float tot = 0.f, tot2 = 0.f;
#pragma unroll
    for (int i = 0; i < 8; i++) { tot += rs[i]; tot2 += rss[i]; }
    float mean = tot * (1.f / 1024.f);
    float var  = tot2 * (1.f / 1024.f) - mean * mean;
    float rstd = rsqrtf(var + 1e-5f);
    float4 wv = reinterpret_cast<const float4*>(w)[t];
    float4 bv = reinterpret_cast<const float4*>(b)[t];
    float o0 = (xv.x - mean) * rstd * wv.x + bv.x;
    float o1 = (xv.y - mean) * rstd * wv.y + bv.y;
    float o2 = (xv.z - mean) * rstd * wv.z + bv.z;
    float o3 = (xv.w - mean) * rstd * wv.w + bv.w;
    uint32_t h0, l0, h1, l1;
    split_pack(o0, o1, h0, l0);
    split_pack(o2, o3, h1, l1);
    *reinterpret_cast<uint2*>(reinterpret_cast<char*>(yh) + (size_t)row * 2048 + t * 8) = make_uint2(h0, h1);
    *reinterpret_cast<uint2*>(reinterpret_cast<char*>(yl) + (size_t)row * 2048 + t * 8) = make_uint2(l0, l1);
}

// ---------------- W[n][k] -> W^T[k][n] hi/lo ----------------
__global__ void wsplit(const float* __restrict__ Wq,
                       const float* __restrict__ Wk,
                       const float* __restrict__ Wv)
{
    int wsel = blockIdx.z;
    const float* W = (wsel == 0) ? Wq : (wsel == 1) ? Wk : Wv;
    bf16* th = g_wth[wsel];
    bf16* tl = g_wtl[wsel];
    __shared__ float tile[32][33];
    int k = blockIdx.x * 32 + threadIdx.x;
    int n0 = blockIdx.y * 32;
#pragma unroll
    for (int i = threadIdx.y; i < 32; i += 8)
        tile[i][threadIdx.x] = W[(size_t)(n0 + i) * 1024 + k];
    __syncthreads();
#pragma unroll
    for (int i = threadIdx.y; i < 32; i += 8) {
        float v = tile[threadIdx.x][i];
        __nv_bfloat16 h = __float2bfloat16(v);
        __nv_bfloat16 l = __float2bfloat16(v - __bfloat162float(h));
        size_t idx = (size_t)(blockIdx.x * 32 + i) * 1024 + n0 + threadIdx.x;
        th[idx] = h;
        tl[idx] = l;
    }
}

// ---------------- projection GEMM: C = A @ W^T + bias -> hi/lo planes ----------------
// smem stage: A-hi [128][48B], A-lo, B-hi [16][272B], B-lo
#define G_AHOFF 0
#define G_ALOFF 6144
#define G_BHOFF 12288
#define G_BLOFF 16640
#define G_STAGE 20992

__global__ __launch_bounds__(512, 1) void gemm_tc(int src, int dst,
                                                  const float* __restrict__ bias)
{
    extern __shared__ __align__(16) uint8_t smg[];
    const bf16* Ah = src ? g_aah : g_tah;
    const bf16* Al = src ? g_aal : g_tal;
    const bf16* Bh = g_wth[dst];
    const bf16* Bl = g_wtl[dst];
    bf16* Ch = (dst == 0) ? g_qh : (dst == 1) ? g_kh : g_vh;
    bf16* Cl = (dst == 0) ? g_ql : (dst == 1) ? g_kl : g_vl;

    int t = threadIdx.x, lane = t & 31, warp = t >> 5;       // 16 warps
    int wm = warp >> 2, wn = warp & 3;                        // 4 x 4, tile 32x32
    int bm = blockIdx.x * 128, bn = blockIdx.y * 128;
    uint32_t smb = smem_to_u32(smg);

    bool isA = t < 256;
    int u = t & 255;
    int arow = u >> 1, aseg = u & 1;
    int brow = u >> 4, bseg = u & 15;
    const bf16* agh = Ah + (size_t)(bm + arow) * 1024 + aseg * 8;
    const bf16* agl = Al + (size_t)(bm + arow) * 1024 + aseg * 8;
    const bf16* bgh = Bh + (size_t)brow * 1024 + bn + bseg * 8;
    const bf16* bgl = Bl + (size_t)brow * 1024 + bn + bseg * 8;
    uint32_t a_dst = arow * 48 + aseg * 16;
    uint32_t b_dst = brow * 272 + bseg * 16;

    auto issue = [&](int ch) {
        uint32_t base = smb + (uint32_t)((ch & 3) * G_STAGE);
        if (isA) {
            CP16(base + G_AHOFF + a_dst, agh + ch * 16);
            CP16(base + G_ALOFF + a_dst, agl + ch * 16);
        } else {
            CP16(base + G_BHOFF + b_dst, bgh + (size_t)ch * 16 * 1024);
            CP16(base + G_BLOFF + b_dst, bgl + (size_t)ch * 16 * 1024);
        }
    };

    float acc[2][4][4];
#pragma unroll
    for (int i = 0; i < 2; i++)
#pragma unroll
        for (int j = 0; j < 4; j++)
#pragma unroll
            for (int e = 0; e < 4; e++) acc[i][j][e] = 0.f;

    issue(0); CP_COMMIT();
    issue(1); CP_COMMIT();
    issue(2); CP_COMMIT();

    uint32_t a_off = (lane & 15) * 48 + (lane >> 4) * 16;
    uint32_t b_off = ((lane & 7) + ((lane >> 3) & 1) * 8) * 272 + (lane >> 4) * 16;

    for (int ch = 0; ch < 64; ch++) {
        CP_WAIT(2);
        __syncthreads();
        if (ch + 3 < 64) issue(ch + 3);
        CP_COMMIT();

        uint32_t base = smb + (uint32_t)((ch & 3) * G_STAGE);
        uint32_t ah[2][4], al[2][4], bh2[4][2], bl2[4][2];
#pragma unroll
        for (int mt = 0; mt < 2; mt++) {
            uint32_t r = base + G_AHOFF + (uint32_t)((wm * 32 + mt * 16) * 48) + a_off;
            LDSM_X4(ah[mt][0], ah[mt][1], ah[mt][2], ah[mt][3], r);
            uint32_t rl = base + G_ALOFF + (uint32_t)((wm * 32 + mt * 16) * 48) + a_off;
            LDSM_X4(al[mt][0], al[mt][1], al[mt][2], al[mt][3], rl);
        }
#pragma unroll
        for (int pp = 0; pp < 2; pp++) {
            uint32_t r = base + G_BHOFF + (uint32_t)((wn * 32 + pp * 16) * 2) + b_off;
            LDSM_X4_T(bh2[pp*2][0], bh2[pp*2][1], bh2[pp*2+1][0], bh2[pp*2+1][1], r);
            uint32_t rl = base + G_BLOFF + (uint32_t)((wn * 32 + pp * 16) * 2) + b_off;
            LDSM_X4_T(bl2[pp*2][0], bl2[pp*2][1], bl2[pp*2+1][0], bl2[pp*2+1][1], rl);
        }
#pragma unroll
        for (int mt = 0; mt < 2; mt++)
#pragma unroll
            for (int nt = 0; nt < 4; nt++) {
                mma16816(acc[mt][nt], ah[mt], bh2[nt]);
                mma16816(acc[mt][nt], ah[mt], bl2[nt]);
                mma16816(acc[mt][nt], al[mt], bh2[nt]);
            }
    }

    int lr = lane >> 2, lc = (lane & 3) * 2;
#pragma unroll
    for (int nt = 0; nt < 4; nt++) {
        int col = bn + wn * 32 + nt * 8 + lc;
        float b0 = __ldg(bias + col), b1 = __ldg(bias + col + 1);
#pragma unroll
        for (int mt = 0; mt < 2; mt++) {
            int row = bm + wm * 32 + mt * 16 + lr;
            uint32_t h01, l01;
            split_pack(acc[mt][nt][0] + b0, acc[mt][nt][1] + b1, h01, l01);
            *reinterpret_cast<uint32_t*>(reinterpret_cast<char*>(Ch) + ((size_t)row * 1024 + col) * 2) = h01;
            *reinterpret_cast<uint32_t*>(reinterpret_cast<char*>(Cl) + ((size_t)row * 1024 + col) * 2) = l01;
            split_pack(acc[mt][nt][2] + b0, acc[mt][nt][3] + b1, h01, l01);
            *reinterpret_cast<uint32_t*>(reinterpret_cast<char*>(Ch) + ((size_t)(row + 8) * 1024 + col) * 2) = h01;
            *reinterpret_cast<uint32_t*>(reinterpret_cast<char*>(Cl) + ((size_t)(row + 8) * 1024 + col) * 2) = l01;
        }
    }
}

// ---------------- score+mean: per (b, q-tile, k-tile), loop 16 heads ----------------
// smem per buffer: QH [128][144B], QL, KH, KL  -> 73728 B; double buffered
#define S_QH 0
#define S_QL 18432
#define S_KH 36864
#define S_KL 55296
#define S_BUF 73728

__global__ __launch_bounds__(512, 1) void score_mean_tc(float* __restrict__ amean)
{
    extern __shared__ __align__(16) uint8_t smg[];
    int b = blockIdx.z;
    int q0 = blockIdx.y * 128, k0 = blockIdx.x * 128;
    int t = threadIdx.x, lane = t & 31, warp = t >> 5;       // 16 warps
    int wm = warp >> 2, wn = warp & 3;                        // 32x32 warp tile
    uint32_t smb = smem_to_u32(smg);

    // staging: 4 planes x 128 rows; thread -> (plane, row), 8 CP16 along the row
    int plane = t >> 7, v = t & 127;
    const bf16* srcp;
    uint32_t doff;
    if (plane == 0)      { srcp = g_qh + (size_t)(b * 512 + q0 + v) * 1024;  doff = S_QH + v * 144; }
    else if (plane == 1) { srcp = g_ql + (size_t)(b * 512 + q0 + v) * 1024;  doff = S_QL + v * 144; }
    else if (plane == 2) { srcp = g_kh + (size_t)(b * 1024 + k0 + v) * 1024; doff = S_KH + v * 144; }
    else                 { srcp = g_kl + (size_t)(b * 1024 + k0 + v) * 1024; doff = S_KL + v * 144; }

    auto issue = [&](int h) {
        uint32_t base = smb + (uint32_t)((h & 1) * S_BUF);
        const bf16* s = srcp + h * 64;
#pragma unroll
        for (int seg = 0; seg < 8; seg++)
            CP16(base + doff + seg * 16, s + seg * 8);
    };

    uint32_t a_off = (lane & 15) * 144 + (lane >> 4) * 16;
    uint32_t b_off = ((lane & 7) + ((lane >> 4) & 1) * 8) * 144 + ((lane >> 3) & 1) * 16;

    float am[2][4][4];
#pragma unroll
    for (int i = 0; i < 2; i++)
#pragma unroll
        for (int j = 0; j < 4; j++)
#pragma unroll
            for (int e = 0; e < 4; e++) am[i][j][e] = 0.f;

    int lr = lane >> 2, lc = (lane & 3) * 2;

    issue(0); CP_COMMIT();

    for (int h = 0; h < 16; h++) {
        if (h < 15) { issue(h + 1); CP_COMMIT(); CP_WAIT(1); }
        else        { CP_WAIT(0); }
        __syncthreads();

        uint32_t base = smb + (uint32_t)((h & 1) * S_BUF);
        float acc[2][4][4];
#pragma unroll
        for (int i = 0; i < 2; i++)
#pragma unroll
            for (int j = 0; j < 4; j++)
#pragma unroll
                for (int e = 0; e < 4; e++) acc[i][j][e] = 0.f;

#pragma unroll
        for (int kc = 0; kc < 4; kc++) {
            uint32_t ah[2][4], al[2][4], bh2[4][2], bl2[4][2];
#pragma unroll
            for (int mt = 0; mt < 2; mt++) {
                uint32_t r = base + S_QH + (uint32_t)((wm * 32 + mt * 16) * 144) + kc * 32 + a_off;
                LDSM_X4(ah[mt][0], ah[mt][1], ah[mt][2], ah[mt][3], r);
                uint32_t rl = base + S_QL + (uint32_t)((wm * 32 + mt * 16) * 144) + kc * 32 + a_off;
                LDSM_X4(al[mt][0], al[mt][1], al[mt][2], al[mt][3], rl);
            }
#pragma unroll
            for (int pp = 0; pp < 2; pp++) {
                uint32_t r = base + S_KH + (uint32_t)((wn * 32 + pp * 16) * 144) + kc * 32 + b_off;
                LDSM_X4(bh2[pp*2][0], bh2[pp*2][1], bh2[pp*2+1][0], bh2[pp*2+1][1], r);
                uint32_t rl = base + S_KL + (uint32_t)((wn * 32 + pp * 16) * 144) + kc * 32 + b_off;
                LDSM_X4(bl2[pp*2][0], bl2[pp*2][1], bl2[pp*2+1][0], bl2[pp*2+1][1], rl);
            }
#pragma unroll
            for (int mt = 0; mt < 2; mt++)
#pragma unroll
                for (int nt = 0; nt < 4; nt++) {
                    mma16816(acc[mt][nt], ah[mt], bh2[nt]);
                    mma16816(acc[mt][nt], ah[mt], bl2[nt]);
                    mma16816(acc[mt][nt], al[mt], bh2[nt]);
                }
        }

        // sigmoid, accumulate mean, split + store S
        size_t splane = ((size_t)b * 16 + h) * 524288;
#pragma unroll
        for (int mt = 0; mt < 2; mt++)
#pragma unroll
            for (int nt = 0; nt < 4; nt++) {
                float s0 = 1.f / (1.f + __expf(-0.125f * acc[mt][nt][0]));
                float s1 = 1.f / (1.f + __expf(-0.125f * acc[mt][nt][1]));
                float s2 = 1.f / (1.f + __expf(-0.125f * acc[mt][nt][2]));
                float s3 = 1.f / (1.f + __expf(-0.125f * acc[mt][nt][3]));
                am[mt][nt][0] += s0; am[mt][nt][1] += s1;
                am[mt][nt][2] += s2; am[mt][nt][3] += s3;
                int row = q0 + wm * 32 + mt * 16 + lr;
                int col = k0 + wn * 32 + nt * 8 + lc;
                uint32_t h01, l01;
                split_pack(s0, s1, h01, l01);
                *reinterpret_cast<uint32_t*>(reinterpret_cast<char*>(g_sh) + (splane + (size_t)row * 1024 + col) * 2) = h01;
                *reinterpret_cast<uint32_t*>(reinterpret_cast<char*>(g_sl) + (splane + (size_t)row * 1024 + col) * 2) = l01;
                split_pack(s2, s3, h01, l01);
                *reinterpret_cast<uint32_t*>(reinterpret_cast<char*>(g_sh) + (splane + (size_t)(row + 8) * 1024 + col) * 2) = h01;
                *reinterpret_cast<uint32_t*>(reinterpret_cast<char*>(g_sl) + (splane + (size_t)(row + 8) * 1024 + col) * 2) = l01;
            }
        __syncthreads();
    }

    // write amean
#pragma unroll
    for (int mt = 0; mt < 2; mt++)
#pragma unroll
        for (int nt = 0; nt < 4; nt++) {
            int row = q0 + wm * 32 + mt * 16 + lr;
            int col = k0 + wn * 32 + nt * 8 + lc;
            *reinterpret_cast<float2*>(amean + ((size_t)(b * 512) + row) * 1024 + col) =
                make_float2(am[mt][nt][0] * 0.0625f, am[mt][nt][1] * 0.0625f);
            *reinterpret_cast<float2*>(amean + ((size_t)(b * 512) + row + 8) * 1024 + col) =
                make_float2(am[mt][nt][2] * 0.0625f, am[mt][nt][3] * 0.0625f);
        }
}

// ---------------- AV: out = S @ V ----------------
#define A_SH 0
#define A_SL 6144
#define A_VH 12288
#define A_VL 14592
#define A_STAGE 16896

__global__ __launch_bounds__(256, 2) void av_tc(float* __restrict__ out)
{
    extern __shared__ __align__(16) uint8_t smg[];
    int bh = blockIdx.y, b = bh >> 4, h = bh & 15;
    int q0 = blockIdx.x * 128;
    int t = threadIdx.x, lane = t & 31, warp = t >> 5;
    int wm = warp >> 1, wn = warp & 1;
    uint32_t smb = smem_to_u32(smg);

    int srow = t >> 1, sseg = t & 1;
    uint32_t s_dst = srow * 48 + sseg * 16;
    const bf16* sgh = g_sh + ((size_t)bh * 512 + q0 + srow) * 1024 + sseg * 8;
    const bf16* sgl = g_sl + ((size_t)bh * 512 + q0 + srow) * 1024 + sseg * 8;
    int vrow = (t & 127) >> 3, vseg = t & 7;
    uint32_t v_dst = (t < 128 ? A_VH : A_VL) + vrow * 144 + vseg * 16;
    const bf16* vg = (t < 128 ? g_vh : g_vl) + (size_t)(b * 1024 + vrow) * 1024 + h * 64 + vseg * 8;

    auto issue = [&](int ch) {
        uint32_t base = smb + (uint32_t)((ch & 3) * A_STAGE);
        CP16(base + A_SH + s_dst, sgh + ch * 16);
        CP16(base + A_SL + s_dst, sgl + ch * 16);
        CP16(base + v_dst, vg + (size_t)ch * 16 * 1024);
    };

    float acc[2][4][4];
#pragma unroll
    for (int i = 0; i < 2; i++)
#pragma unroll
        for (int j = 0; j < 4; j++)
#pragma unroll
            for (int e = 0; e < 4; e++) acc[i][j][e] = 0.f;

    issue(0); CP_COMMIT();
    issue(1); CP_COMMIT();
    issue(2); CP_COMMIT();

    uint32_t a_off = (lane & 15) * 48 + (lane >> 4) * 16;
    uint32_t b_off = ((lane & 7) + ((lane >> 3) & 1) * 8) * 144 + (lane >> 4) * 16;

    for (int ch = 0; ch < 64; ch++) {
        CP_WAIT(2);
        __syncthreads();
        if (ch + 3 < 64) issue(ch + 3);
        CP_COMMIT();

        uint32_t base = smb + (uint32_t)((ch & 3) * A_STAGE);
        uint32_t ah[2][4], al[2][4], bh2[4][2], bl2[4][2];
#pragma unroll
        for (int mt = 0; mt < 2; mt++) {
            uint32_t r = base + A_SH + (uint32_t)((wm * 32 + mt * 16) * 48) + a_off;
            LDSM_X4(ah[mt][0], ah[mt][1], ah[mt][2], ah[mt][3], r);
            uint32_t rl = base + A_SL + (uint32_t)((wm * 32 + mt * 16) * 48) + a_off;
            LDSM_X4(al[mt][0], al[mt][1], al[mt][2], al[mt][3], rl);
        }
#pragma unroll
        for (int pp = 0; pp < 2; pp++) {
            uint32_t r = base + A_VH + (uint32_t)((wn * 32 + pp * 16) * 2) + b_off;
            LDSM_X4_T(bh2[pp*2][0], bh2[pp*2][1], bh2[pp*2+1][0], bh2[pp*2+1][1], r);
            uint32_t rl = base + A_VL + (uint32_t)((wn * 32 + pp * 16) * 2) + b_off;
            LDSM_X4_T(bl2[pp*2][0], bl2[pp*2][1], bl2[pp*2+1][0], bl2[pp*2+1][1], rl);
        }
#pragma unroll
        for (int mt = 0; mt < 2; mt++)
#pragma unroll
            for (int nt = 0; nt < 4; nt++) {
                mma16816(acc[mt][nt], ah[mt], bh2[nt]);
                mma16816(acc[mt][nt], ah[mt], bl2[nt]);
                mma16816(acc[mt][nt], al[mt], bh2[nt]);
            }
    }

    int lr = lane >> 2, lc = (lane & 3) * 2;
#pragma unroll
    for (int nt = 0; nt < 4; nt++) {
        int col = h * 64 + wn * 32 + nt * 8 + lc;
#pragma unroll
        for (int mt = 0; mt < 2; mt++) {
            int row = b * 512 + q0 + wm * 32 + mt * 16 + lr;
            *reinterpret_cast<float2*>(out + (size_t)row * 1024 + col) =
                make_float2(acc[mt][nt][0], acc[mt][nt][1]);
            *reinterpret_cast<float2*>(out + (size_t)(row + 8) * 1024 + col) =
                make_float2(acc[mt][nt][2], acc[mt][nt][3]);
        }
    }
}

// ---------------- launch ----------------
extern "C" void kernel_launch(void* const* d_in, const int* in_sizes, int n_in,
                              void* d_out, int out_size)
{
    (void)in_sizes; (void)n_in; (void)out_size;
    const float* text = (const float*)d_in[0];
    const float* av   = (const float*)d_in[1];
    const float* tn_w = (const float*)d_in[2];
    const float* tn_b = (const float*)d_in[3];
    const float* an_w = (const float*)d_in[4];
    const float* an_b = (const float*)d_in[5];
    const float* Wq   = (const float*)d_in[6];
    const float* bq   = (const float*)d_in[7];
    const float* Wk   = (const float*)d_in[8];
    const float* bk   = (const float*)d_in[9];
    const float* Wv   = (const float*)d_in[10];
    const float* bv   = (const float*)d_in[11];

    float* out   = (float*)d_out;
    float* amean = out + (size_t)BS * NW * 1024;

    static int attr_done = 0;
    if (!attr_done) {
        cudaFuncSetAttribute(gemm_tc,       cudaFuncAttributeMaxDynamicSharedMemorySize, 4 * G_STAGE);
        cudaFuncSetAttribute(score_mean_tc, cudaFuncAttributeMaxDynamicSharedMemorySize, 2 * S_BUF);
        cudaFuncSetAttribute(av_tc,         cudaFuncAttributeMaxDynamicSharedMemorySize, 4 * A_STAGE);
        attr_done = 1;
    }

    ln_split<<<BS * NW, 256>>>(text, tn_w, tn_b, 0);
    ln_split<<<BS * NV, 256>>>(av, an_w, an_b, 1);
    wsplit<<<dim3(32, 32, 3), dim3(32, 8)>>>(Wq, Wk, Wv);

    gemm_tc<<<dim3(32, 8), 512, 4 * G_STAGE>>>(0, 0, bq);
    gemm_tc<<<dim3(64, 8), 512, 4 * G_STAGE>>>(1, 1, bk);
    gemm_tc<<<dim3(64, 8), 512, 4 * G_STAGE>>>(1, 2, bv);

    score_mean_tc<<<dim3(8, 4, 8), 512, 2 * S_BUF>>>(amean);
    av_tc<<<dim3(4, 128), 256, 4 * A_STAGE>>>(out);
}